// round 8
// baseline (speedup 1.0000x reference)
#include <cuda_runtime.h>
#include <math.h>
#include <stdint.h>

// ---------------------------------------------------------------------------
// Problem constants
// ---------------------------------------------------------------------------
namespace {
constexpr int BATCH = 32;
constexpr int HH    = 56;
constexpr int WWd   = 56;
constexpr int C     = 512;
constexpr int NH    = 16;
constexpr int WS    = 7;
constexpr int SSH   = 3;                 // shift size
constexpr int HD    = C / NH;            // 32
constexpr int NT    = WS * WS;           // 49 tokens per window
constexpr int NWIN  = (HH / WS) * (WWd / WS);  // 64 windows per image
constexpr int GWIN  = BATCH * NWIN;      // 2048 windows total
constexpr int M     = GWIN * NT;         // 100352 rows
constexpr float SCALE = 0.17677669529663687f;  // HD^-0.5
constexpr float EPS   = 1e-5f;
constexpr int RB0 = HH - WS;  // 49
constexpr int RB1 = HH - SSH; // 53
}

// ---------------------------------------------------------------------------
// Scratch (device globals: allocation-free rule)
// ---------------------------------------------------------------------------
__device__ __align__(16) float g_xw  [(size_t)M * C];
__device__ __align__(16) float g_q   [(size_t)GWIN * NH * NT * HD];
__device__ __align__(16) float g_k   [(size_t)GWIN * NH * NT * HD];
__device__ __align__(16) float g_v   [(size_t)GWIN * NH * NT * HD];
__device__ __align__(16) float g_o   [(size_t)M * C];
__device__ __align__(16) float g_xres[(size_t)M * C];
__device__ __align__(16) float g_h1  [(size_t)M * 4 * C];

// ---------------------------------------------------------------------------
// LayerNorm (one row per block, 256 threads)
// ---------------------------------------------------------------------------
template<bool SHIFT>
__global__ void __launch_bounds__(256) ln_kernel(const float* __restrict__ src,
                                                 const float* __restrict__ w,
                                                 const float* __restrict__ b,
                                                 float* __restrict__ dst)
{
    int row = blockIdx.x;
    const float* sp;
    if (SHIFT) {
        int win = row / NT, tok = row - win * NT;
        int bi = win >> 6, wi = (win >> 3) & 7, wj = win & 7;
        int yi = tok / WS, xi = tok - yi * WS;
        int h0 = (wi * WS + yi + SSH) % HH;
        int w0 = (wj * WS + xi + SSH) % WWd;
        sp = src + ((size_t)bi * (HH * WWd) + h0 * WWd + w0) * C;
    } else {
        sp = src + (size_t)row * C;
    }
    int t = threadIdx.x;
    float v0 = sp[t], v1 = sp[t + 256];
    float s = v0 + v1, s2 = v0 * v0 + v1 * v1;
#pragma unroll
    for (int o = 16; o; o >>= 1) {
        s  += __shfl_xor_sync(0xffffffffu, s,  o);
        s2 += __shfl_xor_sync(0xffffffffu, s2, o);
    }
    __shared__ float red[16];
    if ((t & 31) == 0) { red[t >> 5] = s; red[(t >> 5) + 8] = s2; }
    __syncthreads();
    float S = 0.f, S2 = 0.f;
#pragma unroll
    for (int i = 0; i < 8; i++) { S += red[i]; S2 += red[i + 8]; }
    float mean = S * (1.0f / C);
    float var  = S2 * (1.0f / C) - mean * mean;
    float r = rsqrtf(var + EPS);
    float* dp = dst + (size_t)row * C;
    dp[t]       = (v0 - mean) * r * w[t]       + b[t];
    dp[t + 256] = (v1 - mean) * r * w[t + 256] + b[t + 256];
}

// ---------------------------------------------------------------------------
// TF32 tensor-core GEMM:  Cmat[m][n] = sum_k A[m][k] * Bw[n][k]  (+ epilogue)
// 128x128 CTA tile, BK=16, 256 threads, warp tile 64x32 via m16n8k8 mma.
// Tiles are staged into smem in FRAGMENT ORDER:
//   A:  As[buf][kstep][mfrag(8)][128 floats] ; thread reads its 4 A regs as
//       one LDS.128 at a 16B-granule XOR-swizzled lane index.
//   B:  Bs[buf][kstep][nfrag(16)][72 floats]; thread reads 2 B regs as LDS.64.
// ---------------------------------------------------------------------------
__device__ __forceinline__ float to_tf32(float x) {
    uint32_t u; asm("cvt.rna.tf32.f32 %0, %1;" : "=r"(u) : "f"(x));
    return __uint_as_float(u);
}

template<int EPI, int K>
__global__ void __launch_bounds__(256, 2) gemm_tf32(
    const float* __restrict__ A, const float* __restrict__ Bw,
    const float* __restrict__ bias,
    const float* __restrict__ extra,
    float* __restrict__ out0, float* __restrict__ out1, float* __restrict__ out2)
{
    __shared__ __align__(16) float As[2][2][8][128];   // 16 KB
    __shared__ __align__(16) float Bs[2][2][16][72];   // 18 KB

    const int m0 = blockIdx.y * 128;
    const int n0 = blockIdx.x * 128;
    const int t    = threadIdx.x;
    const int warp = t >> 5, lane = t & 31;
    const int wm = warp >> 2, wn = warp & 3;     // warp grid 2 x 4
    const int g  = lane >> 2, tg = lane & 3;     // mma quad layout
    const int rl = lane ^ ((lane >> 2) & 3);     // swizzled A read lane

    // staging assignment: thread -> (row in tile, k-step)
    const int srow = t >> 1;                     // 0..127
    const int sks  = t & 1;                      // 0..1
    const float* Ag = A  + (size_t)(m0 + srow) * K + sks * 8;
    const float* Bg = Bw + (size_t)(n0 + srow) * K + sks * 8;
    const int a_mf = srow >> 4, a_m8 = (srow >> 3) & 1, a_g = srow & 7;
    const int b_nf = srow >> 3,                  b_g = srow & 7;
    int aw[4];
#pragma unroll
    for (int q = 0; q < 4; q++)
        aw[q] = (((a_g * 4 + q) ^ (a_g & 3)) << 2) + a_m8;

    float acc[4][4][4];
#pragma unroll
    for (int i = 0; i < 4; i++)
#pragma unroll
        for (int j = 0; j < 4; j++)
#pragma unroll
            for (int c = 0; c < 4; c++) acc[i][j][c] = 0.f;

    constexpr int ITERS = K / 16;

    float4 av0, av1, bv0, bv1;
    av0 = *(const float4*)(Ag);
    av1 = *(const float4*)(Ag + 4);
    bv0 = *(const float4*)(Bg);
    bv1 = *(const float4*)(Bg + 4);

    auto stage = [&](int buf) {
        float* ap = &As[buf][sks][a_mf][0];
        ap[aw[0]]     = to_tf32(av0.x);
        ap[aw[1]]     = to_tf32(av0.y);
        ap[aw[2]]     = to_tf32(av0.z);
        ap[aw[3]]     = to_tf32(av0.w);
        ap[aw[0] + 2] = to_tf32(av1.x);
        ap[aw[1] + 2] = to_tf32(av1.y);
        ap[aw[2] + 2] = to_tf32(av1.z);
        ap[aw[3] + 2] = to_tf32(av1.w);
        float* bp = &Bs[buf][sks][b_nf][b_g * 8];
        float4 w0 = make_float4(to_tf32(bv0.x), to_tf32(bv1.x),
                                to_tf32(bv0.y), to_tf32(bv1.y));
        float4 w1 = make_float4(to_tf32(bv0.z), to_tf32(bv1.z),
                                to_tf32(bv0.w), to_tf32(bv1.w));
        *(float4*)bp       = w0;
        *(float4*)(bp + 4) = w1;
    };

    stage(0);
    __syncthreads();

    for (int it = 0; it < ITERS; ++it) {
        const int buf = it & 1;
        if (it + 1 < ITERS) {
            const float* ag = Ag + (it + 1) * 16;
            const float* bg = Bg + (it + 1) * 16;
            av0 = *(const float4*)ag;       av1 = *(const float4*)(ag + 4);
            bv0 = *(const float4*)bg;       bv1 = *(const float4*)(bg + 4);
        }
#pragma unroll
        for (int ks = 0; ks < 2; ks++) {
            uint32_t af[4][4];
            uint32_t bf[4][2];
#pragma unroll
            for (int mf = 0; mf < 4; mf++) {
                float4 v = *(const float4*)&As[buf][ks][wm * 4 + mf][rl * 4];
                af[mf][0] = __float_as_uint(v.x);
                af[mf][1] = __float_as_uint(v.y);
                af[mf][2] = __float_as_uint(v.z);
                af[mf][3] = __float_as_uint(v.w);
            }
#pragma unroll
            for (int nf = 0; nf < 4; nf++) {
                float2 v = *(const float2*)&Bs[buf][ks][wn * 4 + nf][lane * 2];
                bf[nf][0] = __float_as_uint(v.x);
                bf[nf][1] = __float_as_uint(v.y);
            }
#pragma unroll
            for (int mf = 0; mf < 4; mf++)
#pragma unroll
                for (int nf = 0; nf < 4; nf++)
                    asm volatile(
                        "mma.sync.aligned.m16n8k8.row.col.f32.tf32.tf32.f32 "
                        "{%0,%1,%2,%3}, {%4,%5,%6,%7}, {%8,%9}, {%0,%1,%2,%3};\n"
                        : "+f"(acc[mf][nf][0]), "+f"(acc[mf][nf][1]),
                          "+f"(acc[mf][nf][2]), "+f"(acc[mf][nf][3])
                        : "r"(af[mf][0]), "r"(af[mf][1]),
                          "r"(af[mf][2]), "r"(af[mf][3]),
                          "r"(bf[nf][0]), "r"(bf[nf][1]));
        }
        if (it + 1 < ITERS) {
            stage((it + 1) & 1);
            __syncthreads();
        }
    }

    // epilogue
#pragma unroll
    for (int mf = 0; mf < 4; mf++)
#pragma unroll
    for (int nf = 0; nf < 4; nf++)
#pragma unroll
    for (int cr = 0; cr < 4; cr++) {
        int m = m0 + wm * 64 + mf * 16 + g + ((cr >> 1) << 3);
        int n = n0 + wn * 32 + nf * 8 + tg * 2 + (cr & 1);
        float val = acc[mf][nf][cr] + bias[n];
        if (EPI == 0) {
            int which = n >> 9, cc = n & 511;
            int head = cc >> 5, d = cc & 31;
            int win = m / NT, tok = m - win * NT;
            size_t idx = (((size_t)win * NH + head) * NT + tok) * HD + d;
            if (which == 0)      out0[idx] = val * SCALE;
            else if (which == 1) out1[idx] = val;
            else                 out2[idx] = val;
        } else if (EPI == 1) {
            int win = m / NT, tok = m - win * NT;
            int bi = win >> 6, wi = (win >> 3) & 7, wj = win & 7;
            int yi = tok / WS, xi = tok - yi * WS;
            int h0 = (wi * WS + yi + SSH) % HH;
            int w0 = (wj * WS + xi + SSH) % WWd;
            size_t idx = ((size_t)bi * (HH * WWd) + h0 * WWd + w0) * C + n;
            out0[idx] = extra[idx] + val;
        } else if (EPI == 2) {
            float gl = 0.5f * val * (1.0f + erff(val * 0.70710678118654752f));
            out0[(size_t)m * (4 * C) + n] = gl;
        } else {
            size_t idx = (size_t)m * C + n;
            out0[idx] = extra[idx] + val;
        }
    }
}

// ---------------------------------------------------------------------------
// Windowed attention: one block per (window, head). 128 threads.
// ---------------------------------------------------------------------------
__global__ void __launch_bounds__(128) attn_kernel(
    const float* __restrict__ q, const float* __restrict__ k,
    const float* __restrict__ v, const float* __restrict__ rp,
    float* __restrict__ o)
{
    int wh = blockIdx.x;
    int win = wh >> 4, head = wh & 15;

    __shared__ float Qs[NT][HD], Ks[NT][HD], Vs[NT][HD];
    __shared__ float S[NT][NT];

    const size_t base = (size_t)wh * NT * HD;
    int t = threadIdx.x;
    for (int i = t; i < NT * HD; i += 128) {
        Qs[i / HD][i % HD] = q[base + i];
        Ks[i / HD][i % HD] = k[base + i];
        Vs[i / HD][i % HD] = v[base + i];
    }
    __syncthreads();

    int wi = (win >> 3) & 7, wj = win & 7;
    for (int idx = t; idx < NT * NT; idx += 128) {
        int r = idx / NT, c = idx - r * NT;
        float s = 0.f;
#pragma unroll
        for (int d = 0; d < HD; d++) s = fmaf(Qs[r][d], Ks[c][d], s);
        int yr = r / WS, xr = r - yr * WS;
        int yc = c / WS, xc = c - yc * WS;
        s += rp[((yr - yc + WS - 1) * (2 * WS - 1) + (xr - xc + WS - 1)) * NH + head];
        int hr = wi * WS + yr, wr = wj * WS + xr;
        int hc = wi * WS + yc, wc = wj * WS + xc;
        int ra = (hr < RB0 ? 0 : (hr < RB1 ? 1 : 2)) * 3 + (wr < RB0 ? 0 : (wr < RB1 ? 1 : 2));
        int rb = (hc < RB0 ? 0 : (hc < RB1 ? 1 : 2)) * 3 + (wc < RB0 ? 0 : (wc < RB1 ? 1 : 2));
        if (ra != rb) s -= 100.0f;
        S[r][c] = s;
    }
    __syncthreads();

    int warp = t >> 5, lane = t & 31;
    for (int r = warp; r < NT; r += 4) {
        float mx = -1e30f;
        for (int c = lane; c < NT; c += 32) mx = fmaxf(mx, S[r][c]);
#pragma unroll
        for (int off = 16; off; off >>= 1) mx = fmaxf(mx, __shfl_xor_sync(0xffffffffu, mx, off));
        float sum = 0.f;
        for (int c = lane; c < NT; c += 32) {
            float e = __expf(S[r][c] - mx);
            S[r][c] = e;
            sum += e;
        }
#pragma unroll
        for (int off = 16; off; off >>= 1) sum += __shfl_xor_sync(0xffffffffu, sum, off);
        float inv = 1.0f / sum;
        for (int c = lane; c < NT; c += 32) S[r][c] *= inv;
    }
    __syncthreads();

    for (int idx = t; idx < NT * HD; idx += 128) {
        int r = idx >> 5, d = idx & 31;
        float s = 0.f;
#pragma unroll
        for (int c = 0; c < NT; c++) s = fmaf(S[r][c], Vs[c][d], s);
        o[((size_t)win * NT + r) * C + head * HD + d] = s;
    }
}

// ---------------------------------------------------------------------------
// Launch
// ---------------------------------------------------------------------------
extern "C" void kernel_launch(void* const* d_in, const int* in_sizes, int n_in,
                              void* d_out, int out_size)
{
    (void)in_sizes; (void)n_in; (void)out_size;
    const float* x     = (const float*)d_in[0];
    const float* n1w   = (const float*)d_in[1];
    const float* n1b   = (const float*)d_in[2];
    const float* qkv_w = (const float*)d_in[3];
    const float* qkv_b = (const float*)d_in[4];
    const float* rp    = (const float*)d_in[5];
    const float* out_w = (const float*)d_in[6];
    const float* out_b = (const float*)d_in[7];
    const float* n2w   = (const float*)d_in[8];
    const float* n2b   = (const float*)d_in[9];
    const float* fc1_w = (const float*)d_in[10];
    const float* fc1_b = (const float*)d_in[11];
    const float* fc2_w = (const float*)d_in[12];
    const float* fc2_b = (const float*)d_in[13];
    float* out = (float*)d_out;

    float *xw, *q, *k, *v, *o, *xres, *h1;
    cudaGetSymbolAddress((void**)&xw,   g_xw);
    cudaGetSymbolAddress((void**)&q,    g_q);
    cudaGetSymbolAddress((void**)&k,    g_k);
    cudaGetSymbolAddress((void**)&v,    g_v);
    cudaGetSymbolAddress((void**)&o,    g_o);
    cudaGetSymbolAddress((void**)&xres, g_xres);
    cudaGetSymbolAddress((void**)&h1,   g_h1);

    const int MT = M / 128;  // 784 m-tiles

    // 1. LN1 + shift + window partition
    ln_kernel<true><<<M, 256>>>(x, n1w, n1b, xw);
    // 2. qkv GEMM -> Q/K/V (head-major)
    gemm_tf32<0, 512><<<dim3(12, MT), 256>>>(xw, qkv_w, qkv_b, nullptr, q, k, v);
    // 3. windowed attention
    attn_kernel<<<GWIN * NH, 128>>>(q, k, v, rp, o);
    // 4. output projection + window reverse + unshift + residual
    gemm_tf32<1, 512><<<dim3(4, MT), 256>>>(o, out_w, out_b, x, xres, nullptr, nullptr);
    // 5. LN2
    ln_kernel<false><<<M, 256>>>(xres, n2w, n2b, xw);
    // 6. fc1 + GELU
    gemm_tf32<2, 512><<<dim3(16, MT), 256>>>(xw, fc1_w, fc1_b, nullptr, h1, nullptr, nullptr);
    // 7. fc2 + residual -> out
    gemm_tf32<3, 2048><<<dim3(4, MT), 256>>>(h1, fc2_w, fc2_b, xres, out, nullptr, nullptr);
}

// round 9
// speedup vs baseline: 1.0001x; 1.0001x over previous
#include <cuda_runtime.h>
#include <math.h>
#include <stdint.h>

// ---------------------------------------------------------------------------
// Problem constants
// ---------------------------------------------------------------------------
namespace {
constexpr int BATCH = 32;
constexpr int HH    = 56;
constexpr int WWd   = 56;
constexpr int C     = 512;
constexpr int NH    = 16;
constexpr int WS    = 7;
constexpr int SSH   = 3;                 // shift size
constexpr int HD    = C / NH;            // 32
constexpr int NT    = WS * WS;           // 49 tokens per window
constexpr int NWIN  = (HH / WS) * (WWd / WS);  // 64 windows per image
constexpr int GWIN  = BATCH * NWIN;      // 2048 windows total
constexpr int M     = GWIN * NT;         // 100352 rows
constexpr float SCALE = 0.17677669529663687f;  // HD^-0.5
constexpr float EPS   = 1e-5f;
constexpr int RB0 = HH - WS;  // 49
constexpr int RB1 = HH - SSH; // 53
}

// ---------------------------------------------------------------------------
// Scratch (device globals: allocation-free rule)
// ---------------------------------------------------------------------------
__device__ __align__(16) float g_xw  [(size_t)M * C];
__device__ __align__(16) float g_q   [(size_t)GWIN * NH * NT * HD];
__device__ __align__(16) float g_k   [(size_t)GWIN * NH * NT * HD];
__device__ __align__(16) float g_v   [(size_t)GWIN * NH * NT * HD];
__device__ __align__(16) float g_o   [(size_t)M * C];
__device__ __align__(16) float g_xres[(size_t)M * C];
__device__ __align__(16) float g_h1  [(size_t)M * 4 * C];

// ---------------------------------------------------------------------------
// LayerNorm (one row per block, 256 threads)
// ---------------------------------------------------------------------------
template<bool SHIFT>
__global__ void __launch_bounds__(256) ln_kernel(const float* __restrict__ src,
                                                 const float* __restrict__ w,
                                                 const float* __restrict__ b,
                                                 float* __restrict__ dst)
{
    int row = blockIdx.x;
    const float* sp;
    if (SHIFT) {
        int win = row / NT, tok = row - win * NT;
        int bi = win >> 6, wi = (win >> 3) & 7, wj = win & 7;
        int yi = tok / WS, xi = tok - yi * WS;
        int h0 = (wi * WS + yi + SSH) % HH;
        int w0 = (wj * WS + xi + SSH) % WWd;
        sp = src + ((size_t)bi * (HH * WWd) + h0 * WWd + w0) * C;
    } else {
        sp = src + (size_t)row * C;
    }
    int t = threadIdx.x;
    float v0 = sp[t], v1 = sp[t + 256];
    float s = v0 + v1, s2 = v0 * v0 + v1 * v1;
#pragma unroll
    for (int o = 16; o; o >>= 1) {
        s  += __shfl_xor_sync(0xffffffffu, s,  o);
        s2 += __shfl_xor_sync(0xffffffffu, s2, o);
    }
    __shared__ float red[16];
    if ((t & 31) == 0) { red[t >> 5] = s; red[(t >> 5) + 8] = s2; }
    __syncthreads();
    float S = 0.f, S2 = 0.f;
#pragma unroll
    for (int i = 0; i < 8; i++) { S += red[i]; S2 += red[i + 8]; }
    float mean = S * (1.0f / C);
    float var  = S2 * (1.0f / C) - mean * mean;
    float r = rsqrtf(var + EPS);
    float* dp = dst + (size_t)row * C;
    dp[t]       = (v0 - mean) * r * w[t]       + b[t];
    dp[t + 256] = (v1 - mean) * r * w[t + 256] + b[t + 256];
}

// ---------------------------------------------------------------------------
// TF32 tensor-core GEMM:  Cmat[m][n] = sum_k A[m][k] * Bw[n][k]  (+ epilogue)
// 128x128 CTA tile, BK=16, 256 threads, warp tile 64x32 via m16n8k8 mma.
// Tiles are staged into smem in FRAGMENT ORDER:
//   A:  As[buf][kstep][mfrag(8)][128 floats] ; thread reads its 4 A regs as
//       one LDS.128 at a 16B-granule XOR-swizzled lane index.
//   B:  Bs[buf][kstep][nfrag(16)][72 floats]; thread reads 2 B regs as LDS.64.
// ---------------------------------------------------------------------------
__device__ __forceinline__ float to_tf32(float x) {
    uint32_t u; asm("cvt.rna.tf32.f32 %0, %1;" : "=r"(u) : "f"(x));
    return __uint_as_float(u);
}

template<int EPI, int K>
__global__ void __launch_bounds__(256, 2) gemm_tf32(
    const float* __restrict__ A, const float* __restrict__ Bw,
    const float* __restrict__ bias,
    const float* __restrict__ extra,
    float* __restrict__ out0, float* __restrict__ out1, float* __restrict__ out2)
{
    __shared__ __align__(16) float As[2][2][8][128];   // 16 KB
    __shared__ __align__(16) float Bs[2][2][16][72];   // 18 KB

    const int m0 = blockIdx.y * 128;
    const int n0 = blockIdx.x * 128;
    const int t    = threadIdx.x;
    const int warp = t >> 5, lane = t & 31;
    const int wm = warp >> 2, wn = warp & 3;     // warp grid 2 x 4
    const int g  = lane >> 2, tg = lane & 3;     // mma quad layout
    const int rl = lane ^ ((lane >> 2) & 3);     // swizzled A read lane

    // staging assignment: thread -> (row in tile, k-step)
    const int srow = t >> 1;                     // 0..127
    const int sks  = t & 1;                      // 0..1
    const float* Ag = A  + (size_t)(m0 + srow) * K + sks * 8;
    const float* Bg = Bw + (size_t)(n0 + srow) * K + sks * 8;
    const int a_mf = srow >> 4, a_m8 = (srow >> 3) & 1, a_g = srow & 7;
    const int b_nf = srow >> 3,                  b_g = srow & 7;
    int aw[4];
#pragma unroll
    for (int q = 0; q < 4; q++)
        aw[q] = (((a_g * 4 + q) ^ (a_g & 3)) << 2) + a_m8;

    float acc[4][4][4];
#pragma unroll
    for (int i = 0; i < 4; i++)
#pragma unroll
        for (int j = 0; j < 4; j++)
#pragma unroll
            for (int c = 0; c < 4; c++) acc[i][j][c] = 0.f;

    constexpr int ITERS = K / 16;

    float4 av0, av1, bv0, bv1;
    av0 = *(const float4*)(Ag);
    av1 = *(const float4*)(Ag + 4);
    bv0 = *(const float4*)(Bg);
    bv1 = *(const float4*)(Bg + 4);

    auto stage = [&](int buf) {
        float* ap = &As[buf][sks][a_mf][0];
        ap[aw[0]]     = to_tf32(av0.x);
        ap[aw[1]]     = to_tf32(av0.y);
        ap[aw[2]]     = to_tf32(av0.z);
        ap[aw[3]]     = to_tf32(av0.w);
        ap[aw[0] + 2] = to_tf32(av1.x);
        ap[aw[1] + 2] = to_tf32(av1.y);
        ap[aw[2] + 2] = to_tf32(av1.z);
        ap[aw[3] + 2] = to_tf32(av1.w);
        float* bp = &Bs[buf][sks][b_nf][b_g * 8];
        float4 w0 = make_float4(to_tf32(bv0.x), to_tf32(bv1.x),
                                to_tf32(bv0.y), to_tf32(bv1.y));
        float4 w1 = make_float4(to_tf32(bv0.z), to_tf32(bv1.z),
                                to_tf32(bv0.w), to_tf32(bv1.w));
        *(float4*)bp       = w0;
        *(float4*)(bp + 4) = w1;
    };

    stage(0);
    __syncthreads();

    for (int it = 0; it < ITERS; ++it) {
        const int buf = it & 1;
        if (it + 1 < ITERS) {
            const float* ag = Ag + (it + 1) * 16;
            const float* bg = Bg + (it + 1) * 16;
            av0 = *(const float4*)ag;       av1 = *(const float4*)(ag + 4);
            bv0 = *(const float4*)bg;       bv1 = *(const float4*)(bg + 4);
        }
#pragma unroll
        for (int ks = 0; ks < 2; ks++) {
            uint32_t af[4][4];
            uint32_t bf[4][2];
#pragma unroll
            for (int mf = 0; mf < 4; mf++) {
                float4 v = *(const float4*)&As[buf][ks][wm * 4 + mf][rl * 4];
                af[mf][0] = __float_as_uint(v.x);
                af[mf][1] = __float_as_uint(v.y);
                af[mf][2] = __float_as_uint(v.z);
                af[mf][3] = __float_as_uint(v.w);
            }
#pragma unroll
            for (int nf = 0; nf < 4; nf++) {
                float2 v = *(const float2*)&Bs[buf][ks][wn * 4 + nf][lane * 2];
                bf[nf][0] = __float_as_uint(v.x);
                bf[nf][1] = __float_as_uint(v.y);
            }
#pragma unroll
            for (int mf = 0; mf < 4; mf++)
#pragma unroll
                for (int nf = 0; nf < 4; nf++)
                    asm volatile(
                        "mma.sync.aligned.m16n8k8.row.col.f32.tf32.tf32.f32 "
                        "{%0,%1,%2,%3}, {%4,%5,%6,%7}, {%8,%9}, {%0,%1,%2,%3};\n"
                        : "+f"(acc[mf][nf][0]), "+f"(acc[mf][nf][1]),
                          "+f"(acc[mf][nf][2]), "+f"(acc[mf][nf][3])
                        : "r"(af[mf][0]), "r"(af[mf][1]),
                          "r"(af[mf][2]), "r"(af[mf][3]),
                          "r"(bf[nf][0]), "r"(bf[nf][1]));
        }
        if (it + 1 < ITERS) {
            stage((it + 1) & 1);
            __syncthreads();
        }
    }

    // epilogue
#pragma unroll
    for (int mf = 0; mf < 4; mf++)
#pragma unroll
    for (int nf = 0; nf < 4; nf++)
#pragma unroll
    for (int cr = 0; cr < 4; cr++) {
        int m = m0 + wm * 64 + mf * 16 + g + ((cr >> 1) << 3);
        int n = n0 + wn * 32 + nf * 8 + tg * 2 + (cr & 1);
        float val = acc[mf][nf][cr] + bias[n];
        if (EPI == 0) {
            int which = n >> 9, cc = n & 511;
            int head = cc >> 5, d = cc & 31;
            int win = m / NT, tok = m - win * NT;
            size_t idx = (((size_t)win * NH + head) * NT + tok) * HD + d;
            if (which == 0)      out0[idx] = val * SCALE;
            else if (which == 1) out1[idx] = val;
            else                 out2[idx] = val;
        } else if (EPI == 1) {
            int win = m / NT, tok = m - win * NT;
            int bi = win >> 6, wi = (win >> 3) & 7, wj = win & 7;
            int yi = tok / WS, xi = tok - yi * WS;
            int h0 = (wi * WS + yi + SSH) % HH;
            int w0 = (wj * WS + xi + SSH) % WWd;
            size_t idx = ((size_t)bi * (HH * WWd) + h0 * WWd + w0) * C + n;
            out0[idx] = extra[idx] + val;
        } else if (EPI == 2) {
            float gl = 0.5f * val * (1.0f + erff(val * 0.70710678118654752f));
            out0[(size_t)m * (4 * C) + n] = gl;
        } else {
            size_t idx = (size_t)m * C + n;
            out0[idx] = extra[idx] + val;
        }
    }
}

// ---------------------------------------------------------------------------
// Windowed attention: one block per (window, head). 128 threads.
// ---------------------------------------------------------------------------
__global__ void __launch_bounds__(128) attn_kernel(
    const float* __restrict__ q, const float* __restrict__ k,
    const float* __restrict__ v, const float* __restrict__ rp,
    float* __restrict__ o)
{
    int wh = blockIdx.x;
    int win = wh >> 4, head = wh & 15;

    __shared__ float Qs[NT][HD], Ks[NT][HD], Vs[NT][HD];
    __shared__ float S[NT][NT];

    const size_t base = (size_t)wh * NT * HD;
    int t = threadIdx.x;
    for (int i = t; i < NT * HD; i += 128) {
        Qs[i / HD][i % HD] = q[base + i];
        Ks[i / HD][i % HD] = k[base + i];
        Vs[i / HD][i % HD] = v[base + i];
    }
    __syncthreads();

    int wi = (win >> 3) & 7, wj = win & 7;
    for (int idx = t; idx < NT * NT; idx += 128) {
        int r = idx / NT, c = idx - r * NT;
        float s = 0.f;
#pragma unroll
        for (int d = 0; d < HD; d++) s = fmaf(Qs[r][d], Ks[c][d], s);
        int yr = r / WS, xr = r - yr * WS;
        int yc = c / WS, xc = c - yc * WS;
        s += rp[((yr - yc + WS - 1) * (2 * WS - 1) + (xr - xc + WS - 1)) * NH + head];
        int hr = wi * WS + yr, wr = wj * WS + xr;
        int hc = wi * WS + yc, wc = wj * WS + xc;
        int ra = (hr < RB0 ? 0 : (hr < RB1 ? 1 : 2)) * 3 + (wr < RB0 ? 0 : (wr < RB1 ? 1 : 2));
        int rb = (hc < RB0 ? 0 : (hc < RB1 ? 1 : 2)) * 3 + (wc < RB0 ? 0 : (wc < RB1 ? 1 : 2));
        if (ra != rb) s -= 100.0f;
        S[r][c] = s;
    }
    __syncthreads();

    int warp = t >> 5, lane = t & 31;
    for (int r = warp; r < NT; r += 4) {
        float mx = -1e30f;
        for (int c = lane; c < NT; c += 32) mx = fmaxf(mx, S[r][c]);
#pragma unroll
        for (int off = 16; off; off >>= 1) mx = fmaxf(mx, __shfl_xor_sync(0xffffffffu, mx, off));
        float sum = 0.f;
        for (int c = lane; c < NT; c += 32) {
            float e = __expf(S[r][c] - mx);
            S[r][c] = e;
            sum += e;
        }
#pragma unroll
        for (int off = 16; off; off >>= 1) sum += __shfl_xor_sync(0xffffffffu, sum, off);
        float inv = 1.0f / sum;
        for (int c = lane; c < NT; c += 32) S[r][c] *= inv;
    }
    __syncthreads();

    for (int idx = t; idx < NT * HD; idx += 128) {
        int r = idx >> 5, d = idx & 31;
        float s = 0.f;
#pragma unroll
        for (int c = 0; c < NT; c++) s = fmaf(S[r][c], Vs[c][d], s);
        o[((size_t)win * NT + r) * C + head * HD + d] = s;
    }
}

// ---------------------------------------------------------------------------
// Launch
// ---------------------------------------------------------------------------
extern "C" void kernel_launch(void* const* d_in, const int* in_sizes, int n_in,
                              void* d_out, int out_size)
{
    (void)in_sizes; (void)n_in; (void)out_size;
    const float* x     = (const float*)d_in[0];
    const float* n1w   = (const float*)d_in[1];
    const float* n1b   = (const float*)d_in[2];
    const float* qkv_w = (const float*)d_in[3];
    const float* qkv_b = (const float*)d_in[4];
    const float* rp    = (const float*)d_in[5];
    const float* out_w = (const float*)d_in[6];
    const float* out_b = (const float*)d_in[7];
    const float* n2w   = (const float*)d_in[8];
    const float* n2b   = (const float*)d_in[9];
    const float* fc1_w = (const float*)d_in[10];
    const float* fc1_b = (const float*)d_in[11];
    const float* fc2_w = (const float*)d_in[12];
    const float* fc2_b = (const float*)d_in[13];
    float* out = (float*)d_out;

    float *xw, *q, *k, *v, *o, *xres, *h1;
    cudaGetSymbolAddress((void**)&xw,   g_xw);
    cudaGetSymbolAddress((void**)&q,    g_q);
    cudaGetSymbolAddress((void**)&k,    g_k);
    cudaGetSymbolAddress((void**)&v,    g_v);
    cudaGetSymbolAddress((void**)&o,    g_o);
    cudaGetSymbolAddress((void**)&xres, g_xres);
    cudaGetSymbolAddress((void**)&h1,   g_h1);

    const int MT = M / 128;  // 784 m-tiles

    // 1. LN1 + shift + window partition
    ln_kernel<true><<<M, 256>>>(x, n1w, n1b, xw);
    // 2. qkv GEMM -> Q/K/V (head-major)
    gemm_tf32<0, 512><<<dim3(12, MT), 256>>>(xw, qkv_w, qkv_b, nullptr, q, k, v);
    // 3. windowed attention
    attn_kernel<<<GWIN * NH, 128>>>(q, k, v, rp, o);
    // 4. output projection + window reverse + unshift + residual
    gemm_tf32<1, 512><<<dim3(4, MT), 256>>>(o, out_w, out_b, x, xres, nullptr, nullptr);
    // 5. LN2
    ln_kernel<false><<<M, 256>>>(xres, n2w, n2b, xw);
    // 6. fc1 + GELU
    gemm_tf32<2, 512><<<dim3(16, MT), 256>>>(xw, fc1_w, fc1_b, nullptr, h1, nullptr, nullptr);
    // 7. fc2 + residual -> out
    gemm_tf32<3, 2048><<<dim3(4, MT), 256>>>(h1, fc2_w, fc2_b, xres, out, nullptr, nullptr);
}

// round 10
// speedup vs baseline: 1.0003x; 1.0002x over previous
#include <cuda_runtime.h>
#include <math.h>
#include <stdint.h>

// ---------------------------------------------------------------------------
// Problem constants
// ---------------------------------------------------------------------------
namespace {
constexpr int BATCH = 32;
constexpr int HH    = 56;
constexpr int WWd   = 56;
constexpr int C     = 512;
constexpr int NH    = 16;
constexpr int WS    = 7;
constexpr int SSH   = 3;                 // shift size
constexpr int HD    = C / NH;            // 32
constexpr int NT    = WS * WS;           // 49 tokens per window
constexpr int NWIN  = (HH / WS) * (WWd / WS);  // 64 windows per image
constexpr int GWIN  = BATCH * NWIN;      // 2048 windows total
constexpr int M     = GWIN * NT;         // 100352 rows
constexpr float SCALE = 0.17677669529663687f;  // HD^-0.5
constexpr float EPS   = 1e-5f;
constexpr int RB0 = HH - WS;  // 49
constexpr int RB1 = HH - SSH; // 53
}

// ---------------------------------------------------------------------------
// Scratch (device globals: allocation-free rule)
// ---------------------------------------------------------------------------
__device__ __align__(16) float g_xw  [(size_t)M * C];
__device__ __align__(16) float g_q   [(size_t)GWIN * NH * NT * HD];
__device__ __align__(16) float g_k   [(size_t)GWIN * NH * NT * HD];
__device__ __align__(16) float g_v   [(size_t)GWIN * NH * NT * HD];
__device__ __align__(16) float g_o   [(size_t)M * C];
__device__ __align__(16) float g_xres[(size_t)M * C];
__device__ __align__(16) float g_h1  [(size_t)M * 4 * C];

// ---------------------------------------------------------------------------
// LayerNorm (one row per block, 256 threads)
// ---------------------------------------------------------------------------
template<bool SHIFT>
__global__ void __launch_bounds__(256) ln_kernel(const float* __restrict__ src,
                                                 const float* __restrict__ w,
                                                 const float* __restrict__ b,
                                                 float* __restrict__ dst)
{
    int row = blockIdx.x;
    const float* sp;
    if (SHIFT) {
        int win = row / NT, tok = row - win * NT;
        int bi = win >> 6, wi = (win >> 3) & 7, wj = win & 7;
        int yi = tok / WS, xi = tok - yi * WS;
        int h0 = (wi * WS + yi + SSH) % HH;
        int w0 = (wj * WS + xi + SSH) % WWd;
        sp = src + ((size_t)bi * (HH * WWd) + h0 * WWd + w0) * C;
    } else {
        sp = src + (size_t)row * C;
    }
    int t = threadIdx.x;
    float v0 = sp[t], v1 = sp[t + 256];
    float s = v0 + v1, s2 = v0 * v0 + v1 * v1;
#pragma unroll
    for (int o = 16; o; o >>= 1) {
        s  += __shfl_xor_sync(0xffffffffu, s,  o);
        s2 += __shfl_xor_sync(0xffffffffu, s2, o);
    }
    __shared__ float red[16];
    if ((t & 31) == 0) { red[t >> 5] = s; red[(t >> 5) + 8] = s2; }
    __syncthreads();
    float S = 0.f, S2 = 0.f;
#pragma unroll
    for (int i = 0; i < 8; i++) { S += red[i]; S2 += red[i + 8]; }
    float mean = S * (1.0f / C);
    float var  = S2 * (1.0f / C) - mean * mean;
    float r = rsqrtf(var + EPS);
    float* dp = dst + (size_t)row * C;
    dp[t]       = (v0 - mean) * r * w[t]       + b[t];
    dp[t + 256] = (v1 - mean) * r * w[t + 256] + b[t + 256];
}

// ---------------------------------------------------------------------------
// TF32 tensor-core GEMM:  Cmat[m][n] = sum_k A[m][k] * Bw[n][k]  (+ epilogue)
// 128x128 CTA tile, BK=16, 256 threads, warp tile 64x32 via m16n8k8 mma.
// Tiles are staged into smem in FRAGMENT ORDER:
//   A:  As[buf][kstep][mfrag(8)][128 floats] ; thread reads its 4 A regs as
//       one LDS.128 at a 16B-granule XOR-swizzled lane index.
//   B:  Bs[buf][kstep][nfrag(16)][72 floats]; thread reads 2 B regs as LDS.64.
// ---------------------------------------------------------------------------
__device__ __forceinline__ float to_tf32(float x) {
    uint32_t u; asm("cvt.rna.tf32.f32 %0, %1;" : "=r"(u) : "f"(x));
    return __uint_as_float(u);
}

template<int EPI, int K>
__global__ void __launch_bounds__(256, 2) gemm_tf32(
    const float* __restrict__ A, const float* __restrict__ Bw,
    const float* __restrict__ bias,
    const float* __restrict__ extra,
    float* __restrict__ out0, float* __restrict__ out1, float* __restrict__ out2)
{
    __shared__ __align__(16) float As[2][2][8][128];   // 16 KB
    __shared__ __align__(16) float Bs[2][2][16][72];   // 18 KB

    const int m0 = blockIdx.y * 128;
    const int n0 = blockIdx.x * 128;
    const int t    = threadIdx.x;
    const int warp = t >> 5, lane = t & 31;
    const int wm = warp >> 2, wn = warp & 3;     // warp grid 2 x 4
    const int g  = lane >> 2, tg = lane & 3;     // mma quad layout
    const int rl = lane ^ ((lane >> 2) & 3);     // swizzled A read lane

    // staging assignment: thread -> (row in tile, k-step)
    const int srow = t >> 1;                     // 0..127
    const int sks  = t & 1;                      // 0..1
    const float* Ag = A  + (size_t)(m0 + srow) * K + sks * 8;
    const float* Bg = Bw + (size_t)(n0 + srow) * K + sks * 8;
    const int a_mf = srow >> 4, a_m8 = (srow >> 3) & 1, a_g = srow & 7;
    const int b_nf = srow >> 3,                  b_g = srow & 7;
    int aw[4];
#pragma unroll
    for (int q = 0; q < 4; q++)
        aw[q] = (((a_g * 4 + q) ^ (a_g & 3)) << 2) + a_m8;

    float acc[4][4][4];
#pragma unroll
    for (int i = 0; i < 4; i++)
#pragma unroll
        for (int j = 0; j < 4; j++)
#pragma unroll
            for (int c = 0; c < 4; c++) acc[i][j][c] = 0.f;

    constexpr int ITERS = K / 16;

    float4 av0, av1, bv0, bv1;
    av0 = *(const float4*)(Ag);
    av1 = *(const float4*)(Ag + 4);
    bv0 = *(const float4*)(Bg);
    bv1 = *(const float4*)(Bg + 4);

    auto stage = [&](int buf) {
        float* ap = &As[buf][sks][a_mf][0];
        ap[aw[0]]     = to_tf32(av0.x);
        ap[aw[1]]     = to_tf32(av0.y);
        ap[aw[2]]     = to_tf32(av0.z);
        ap[aw[3]]     = to_tf32(av0.w);
        ap[aw[0] + 2] = to_tf32(av1.x);
        ap[aw[1] + 2] = to_tf32(av1.y);
        ap[aw[2] + 2] = to_tf32(av1.z);
        ap[aw[3] + 2] = to_tf32(av1.w);
        float* bp = &Bs[buf][sks][b_nf][b_g * 8];
        float4 w0 = make_float4(to_tf32(bv0.x), to_tf32(bv1.x),
                                to_tf32(bv0.y), to_tf32(bv1.y));
        float4 w1 = make_float4(to_tf32(bv0.z), to_tf32(bv1.z),
                                to_tf32(bv0.w), to_tf32(bv1.w));
        *(float4*)bp       = w0;
        *(float4*)(bp + 4) = w1;
    };

    stage(0);
    __syncthreads();

    for (int it = 0; it < ITERS; ++it) {
        const int buf = it & 1;
        if (it + 1 < ITERS) {
            const float* ag = Ag + (it + 1) * 16;
            const float* bg = Bg + (it + 1) * 16;
            av0 = *(const float4*)ag;       av1 = *(const float4*)(ag + 4);
            bv0 = *(const float4*)bg;       bv1 = *(const float4*)(bg + 4);
        }
#pragma unroll
        for (int ks = 0; ks < 2; ks++) {
            uint32_t af[4][4];
            uint32_t bf[4][2];
#pragma unroll
            for (int mf = 0; mf < 4; mf++) {
                float4 v = *(const float4*)&As[buf][ks][wm * 4 + mf][rl * 4];
                af[mf][0] = __float_as_uint(v.x);
                af[mf][1] = __float_as_uint(v.y);
                af[mf][2] = __float_as_uint(v.z);
                af[mf][3] = __float_as_uint(v.w);
            }
#pragma unroll
            for (int nf = 0; nf < 4; nf++) {
                float2 v = *(const float2*)&Bs[buf][ks][wn * 4 + nf][lane * 2];
                bf[nf][0] = __float_as_uint(v.x);
                bf[nf][1] = __float_as_uint(v.y);
            }
#pragma unroll
            for (int mf = 0; mf < 4; mf++)
#pragma unroll
                for (int nf = 0; nf < 4; nf++)
                    asm volatile(
                        "mma.sync.aligned.m16n8k8.row.col.f32.tf32.tf32.f32 "
                        "{%0,%1,%2,%3}, {%4,%5,%6,%7}, {%8,%9}, {%0,%1,%2,%3};\n"
                        : "+f"(acc[mf][nf][0]), "+f"(acc[mf][nf][1]),
                          "+f"(acc[mf][nf][2]), "+f"(acc[mf][nf][3])
                        : "r"(af[mf][0]), "r"(af[mf][1]),
                          "r"(af[mf][2]), "r"(af[mf][3]),
                          "r"(bf[nf][0]), "r"(bf[nf][1]));
        }
        if (it + 1 < ITERS) {
            stage((it + 1) & 1);
            __syncthreads();
        }
    }

    // epilogue
#pragma unroll
    for (int mf = 0; mf < 4; mf++)
#pragma unroll
    for (int nf = 0; nf < 4; nf++)
#pragma unroll
    for (int cr = 0; cr < 4; cr++) {
        int m = m0 + wm * 64 + mf * 16 + g + ((cr >> 1) << 3);
        int n = n0 + wn * 32 + nf * 8 + tg * 2 + (cr & 1);
        float val = acc[mf][nf][cr] + bias[n];
        if (EPI == 0) {
            int which = n >> 9, cc = n & 511;
            int head = cc >> 5, d = cc & 31;
            int win = m / NT, tok = m - win * NT;
            size_t idx = (((size_t)win * NH + head) * NT + tok) * HD + d;
            if (which == 0)      out0[idx] = val * SCALE;
            else if (which == 1) out1[idx] = val;
            else                 out2[idx] = val;
        } else if (EPI == 1) {
            int win = m / NT, tok = m - win * NT;
            int bi = win >> 6, wi = (win >> 3) & 7, wj = win & 7;
            int yi = tok / WS, xi = tok - yi * WS;
            int h0 = (wi * WS + yi + SSH) % HH;
            int w0 = (wj * WS + xi + SSH) % WWd;
            size_t idx = ((size_t)bi * (HH * WWd) + h0 * WWd + w0) * C + n;
            out0[idx] = extra[idx] + val;
        } else if (EPI == 2) {
            float gl = 0.5f * val * (1.0f + erff(val * 0.70710678118654752f));
            out0[(size_t)m * (4 * C) + n] = gl;
        } else {
            size_t idx = (size_t)m * C + n;
            out0[idx] = extra[idx] + val;
        }
    }
}

// ---------------------------------------------------------------------------
// Windowed attention: one block per (window, head). 128 threads.
// ---------------------------------------------------------------------------
__global__ void __launch_bounds__(128) attn_kernel(
    const float* __restrict__ q, const float* __restrict__ k,
    const float* __restrict__ v, const float* __restrict__ rp,
    float* __restrict__ o)
{
    int wh = blockIdx.x;
    int win = wh >> 4, head = wh & 15;

    __shared__ float Qs[NT][HD], Ks[NT][HD], Vs[NT][HD];
    __shared__ float S[NT][NT];

    const size_t base = (size_t)wh * NT * HD;
    int t = threadIdx.x;
    for (int i = t; i < NT * HD; i += 128) {
        Qs[i / HD][i % HD] = q[base + i];
        Ks[i / HD][i % HD] = k[base + i];
        Vs[i / HD][i % HD] = v[base + i];
    }
    __syncthreads();

    int wi = (win >> 3) & 7, wj = win & 7;
    for (int idx = t; idx < NT * NT; idx += 128) {
        int r = idx / NT, c = idx - r * NT;
        float s = 0.f;
#pragma unroll
        for (int d = 0; d < HD; d++) s = fmaf(Qs[r][d], Ks[c][d], s);
        int yr = r / WS, xr = r - yr * WS;
        int yc = c / WS, xc = c - yc * WS;
        s += rp[((yr - yc + WS - 1) * (2 * WS - 1) + (xr - xc + WS - 1)) * NH + head];
        int hr = wi * WS + yr, wr = wj * WS + xr;
        int hc = wi * WS + yc, wc = wj * WS + xc;
        int ra = (hr < RB0 ? 0 : (hr < RB1 ? 1 : 2)) * 3 + (wr < RB0 ? 0 : (wr < RB1 ? 1 : 2));
        int rb = (hc < RB0 ? 0 : (hc < RB1 ? 1 : 2)) * 3 + (wc < RB0 ? 0 : (wc < RB1 ? 1 : 2));
        if (ra != rb) s -= 100.0f;
        S[r][c] = s;
    }
    __syncthreads();

    int warp = t >> 5, lane = t & 31;
    for (int r = warp; r < NT; r += 4) {
        float mx = -1e30f;
        for (int c = lane; c < NT; c += 32) mx = fmaxf(mx, S[r][c]);
#pragma unroll
        for (int off = 16; off; off >>= 1) mx = fmaxf(mx, __shfl_xor_sync(0xffffffffu, mx, off));
        float sum = 0.f;
        for (int c = lane; c < NT; c += 32) {
            float e = __expf(S[r][c] - mx);
            S[r][c] = e;
            sum += e;
        }
#pragma unroll
        for (int off = 16; off; off >>= 1) sum += __shfl_xor_sync(0xffffffffu, sum, off);
        float inv = 1.0f / sum;
        for (int c = lane; c < NT; c += 32) S[r][c] *= inv;
    }
    __syncthreads();

    for (int idx = t; idx < NT * HD; idx += 128) {
        int r = idx >> 5, d = idx & 31;
        float s = 0.f;
#pragma unroll
        for (int c = 0; c < NT; c++) s = fmaf(S[r][c], Vs[c][d], s);
        o[((size_t)win * NT + r) * C + head * HD + d] = s;
    }
}

// ---------------------------------------------------------------------------
// Launch
// ---------------------------------------------------------------------------
extern "C" void kernel_launch(void* const* d_in, const int* in_sizes, int n_in,
                              void* d_out, int out_size)
{
    (void)in_sizes; (void)n_in; (void)out_size;
    const float* x     = (const float*)d_in[0];
    const float* n1w   = (const float*)d_in[1];
    const float* n1b   = (const float*)d_in[2];
    const float* qkv_w = (const float*)d_in[3];
    const float* qkv_b = (const float*)d_in[4];
    const float* rp    = (const float*)d_in[5];
    const float* out_w = (const float*)d_in[6];
    const float* out_b = (const float*)d_in[7];
    const float* n2w   = (const float*)d_in[8];
    const float* n2b   = (const float*)d_in[9];
    const float* fc1_w = (const float*)d_in[10];
    const float* fc1_b = (const float*)d_in[11];
    const float* fc2_w = (const float*)d_in[12];
    const float* fc2_b = (const float*)d_in[13];
    float* out = (float*)d_out;

    float *xw, *q, *k, *v, *o, *xres, *h1;
    cudaGetSymbolAddress((void**)&xw,   g_xw);
    cudaGetSymbolAddress((void**)&q,    g_q);
    cudaGetSymbolAddress((void**)&k,    g_k);
    cudaGetSymbolAddress((void**)&v,    g_v);
    cudaGetSymbolAddress((void**)&o,    g_o);
    cudaGetSymbolAddress((void**)&xres, g_xres);
    cudaGetSymbolAddress((void**)&h1,   g_h1);

    const int MT = M / 128;  // 784 m-tiles

    // 1. LN1 + shift + window partition
    ln_kernel<true><<<M, 256>>>(x, n1w, n1b, xw);
    // 2. qkv GEMM -> Q/K/V (head-major)
    gemm_tf32<0, 512><<<dim3(12, MT), 256>>>(xw, qkv_w, qkv_b, nullptr, q, k, v);
    // 3. windowed attention
    attn_kernel<<<GWIN * NH, 128>>>(q, k, v, rp, o);
    // 4. output projection + window reverse + unshift + residual
    gemm_tf32<1, 512><<<dim3(4, MT), 256>>>(o, out_w, out_b, x, xres, nullptr, nullptr);
    // 5. LN2
    ln_kernel<false><<<M, 256>>>(xres, n2w, n2b, xw);
    // 6. fc1 + GELU
    gemm_tf32<2, 512><<<dim3(16, MT), 256>>>(xw, fc1_w, fc1_b, nullptr, h1, nullptr, nullptr);
    // 7. fc2 + residual -> out
    gemm_tf32<3, 2048><<<dim3(4, MT), 256>>>(h1, fc2_w, fc2_b, xres, out, nullptr, nullptr);
}